// round 15
// baseline (speedup 1.0000x reference)
#include <cuda_runtime.h>

#define NJ   32
#define TPB  128
#define EPB  (TPB / 2)     // 64 elements per block, 2 threads each
#define OUTC 94

typedef unsigned long long u64;

// ---- dynamic smem float offsets ----
#define S_OUT   0                       // 64*94 = 6016 (flush staging; cfg scratch early)
#define S_BASE  6016                    // 64 x 8
#define S_DB    6528                    // 8 (scalar default-base, padded)
#define S_LIM   6536                    // 32 x 4 (up, lo, rest, pad)
#define S_TGT2  6664                    // 2 pairs x 10 u64 = 40 floats
#define S_PREC  6704                    // 16 leaf-pairs x 12 u64 = 384 floats
#define S_TOTAL 7088                    // 28352 B

#define CFG_PAD 36

// ---- packed f32x2 primitives ----
__device__ __forceinline__ u64 f2pack(float lo, float hi) {
    u64 r;
    asm("mov.b64 %0, {%1, %2};" : "=l"(r)
        : "r"(__float_as_uint(lo)), "r"(__float_as_uint(hi)));
    return r;
}
__device__ __forceinline__ void f2unp(u64 a, float& lo, float& hi) {
    unsigned l, h;
    asm("mov.b64 {%0, %1}, %2;" : "=r"(l), "=r"(h) : "l"(a));
    lo = __uint_as_float(l); hi = __uint_as_float(h);
}
__device__ __forceinline__ u64 f2mul(u64 a, u64 b) {
    u64 r; asm("mul.rn.f32x2 %0, %1, %2;" : "=l"(r) : "l"(a), "l"(b)); return r;
}
__device__ __forceinline__ u64 f2add(u64 a, u64 b) {
    u64 r; asm("add.rn.f32x2 %0, %1, %2;" : "=l"(r) : "l"(a), "l"(b)); return r;
}
__device__ __forceinline__ u64 f2fma(u64 a, u64 b, u64 c) {
    u64 r; asm("fma.rn.f32x2 %0, %1, %2, %3;" : "=l"(r) : "l"(a), "l"(b), "l"(c)); return r;
}

#define C_NEG1  0xBF800000BF800000ULL
#define C_TWO   0x4000000040000000ULL
#define C_NHALF 0xBF000000BF000000ULL

struct Q { float x, y, z, w; };
struct V { float x, y, z; };
struct V2 { u64 x, y, z; };
struct Q2 { u64 x, y, z, w; };

// ================= scalar helpers =================
__device__ __forceinline__ V vcross(V a, V b) {
    return {a.y * b.z - a.z * b.y,
            a.z * b.x - a.x * b.z,
            a.x * b.y - a.y * b.x};
}
__device__ __forceinline__ V qrot(Q q, V t) {
    V v{q.x, q.y, q.z};
    V u = vcross(v, t);
    u.x = fmaf(q.w, t.x, u.x);
    u.y = fmaf(q.w, t.y, u.y);
    u.z = fmaf(q.w, t.z, u.z);
    V c = vcross(v, u);
    return {fmaf(2.0f, c.x, t.x), fmaf(2.0f, c.y, t.y), fmaf(2.0f, c.z, t.z)};
}
__device__ __forceinline__ Q qmul(Q a, Q b) {
    Q r;
    r.w = a.w * b.w - a.x * b.x - a.y * b.y - a.z * b.z;
    r.x = a.w * b.x + b.w * a.x + a.y * b.z - a.z * b.y;
    r.y = a.w * b.y + b.w * a.y + a.z * b.x - a.x * b.z;
    r.z = a.w * b.z + b.w * a.z + a.x * b.y - a.y * b.x;
    return r;
}
__device__ __forceinline__ void se3_comp(V t1, Q q1, V t2, Q q2, V& to, Q& qo) {
    V r = qrot(q1, t2);
    to.x = t1.x + r.x; to.y = t1.y + r.y; to.z = t1.z + r.z;
    qo = qmul(q1, q2);
}
__device__ __forceinline__ float atan2pos(float y, float x) {
    float mn = fminf(y, x), mx = fmaxf(y, x);
    float r  = __fdividef(mn, mx);
    float r2 = r * r;
    float p = fmaf(r2, -0.0117212f,  0.05265332f);
    p = fmaf(r2, p, -0.11643287f);
    p = fmaf(r2, p,  0.19354346f);
    p = fmaf(r2, p, -0.33262347f);
    p = fmaf(r2, p,  0.99997726f);
    float th = r * p;
    return (y > x) ? (1.57079632679489662f - th) : th;
}
__device__ __forceinline__ void se3_log(V t, Q q, V& rho, V& phi) {
    float sgn = (q.w < 0.0f) ? -1.0f : 1.0f;
    float qx = q.x * sgn, qy = q.y * sgn, qz = q.z * sgn, qw = q.w * sgn;
    float nv2 = qx * qx + qy * qy + qz * qz;
    float nv  = sqrtf(fmaxf(nv2, 1e-14f));
    float angle = 2.0f * atan2pos(nv, qw);
    float wsafe = (fabsf(qw) > 1e-8f) ? qw : 1.0f;
    float scale = (nv < 1e-6f) ? __fdividef(2.0f, wsafe) : __fdividef(angle, nv);
    phi = {qx * scale, qy * scale, qz * scale};
    float th2 = angle * angle;
    float abig = __fdividef(1.0f - 0.5f * scale * qw, th2);
    float a = (angle < 1e-4f) ? (1.0f / 12.0f + th2 * (1.0f / 720.0f)) : abig;
    V pt  = vcross(phi, t);
    V ppt = vcross(phi, pt);
    rho = {t.x - 0.5f * pt.x + a * ppt.x,
           t.y - 0.5f * pt.y + a * ppt.y,
           t.z - 0.5f * pt.z + a * ppt.z};
}
__device__ __forceinline__ void pose_err_log(const float* tp, V at, Q aq,
                                             V& rho, V& phi) {
    float4 a = *(const float4*)tp;
    float4 b = *(const float4*)(tp + 4);
    Q qi{-b.x, -b.y, -b.z, b.w};
    V d{at.x - a.x, at.y - a.y, at.z - a.z};
    V pe = qrot(qi, d);
    Q qe = qmul(qi, aq);
    se3_log(pe, qe, rho, phi);
}

// ================= packed helpers (validated R4/R13/R14) =================
__device__ __forceinline__ void log_scalars(float nv2, float qw,
                                            float& scale, float& a) {
    float nv  = sqrtf(fmaxf(nv2, 1e-14f));
    float qwc = fabsf(qw);
    float angle = 2.0f * atan2pos(nv, qwc);
    float wsafe = (qwc > 1e-8f) ? qwc : 1.0f;
    scale = (nv < 1e-6f) ? __fdividef(2.0f, wsafe) : __fdividef(angle, nv);
    float th2  = angle * angle;
    float abig = __fdividef(1.0f - 0.5f * scale * qwc, th2);
    a = (angle < 1e-4f) ? (1.0f / 12.0f + th2 * (1.0f / 720.0f)) : abig;
}

__device__ __forceinline__ void se3_log2(V2 t, Q2 q, V2& rho, V2& phi) {
    const u64 NEG1 = C_NEG1, NHALF = C_NHALF;
    float qwA, qwB; f2unp(q.w, qwA, qwB);
    u64 sg = f2pack(qwA < 0.0f ? -1.0f : 1.0f, qwB < 0.0f ? -1.0f : 1.0f);
    u64 qx = f2mul(q.x, sg), qy = f2mul(q.y, sg), qz = f2mul(q.z, sg);
    u64 nv2 = f2fma(qx, qx, f2fma(qy, qy, f2mul(qz, qz)));
    float n2A, n2B; f2unp(nv2, n2A, n2B);
    float scA, aA, scB, aB;
    log_scalars(n2A, qwA, scA, aA);
    log_scalars(n2B, qwB, scB, aB);
    u64 sc = f2pack(scA, scB), a2 = f2pack(aA, aB);
    phi.x = f2mul(qx, sc); phi.y = f2mul(qy, sc); phi.z = f2mul(qz, sc);
    u64 nx = f2mul(phi.x, NEG1), ny = f2mul(phi.y, NEG1), nz = f2mul(phi.z, NEG1);
    u64 ptx = f2fma(phi.y, t.z, f2mul(nz, t.y));
    u64 pty = f2fma(phi.z, t.x, f2mul(nx, t.z));
    u64 ptz = f2fma(phi.x, t.y, f2mul(ny, t.x));
    u64 px = f2fma(phi.y, ptz, f2mul(nz, pty));
    u64 py = f2fma(phi.z, ptx, f2mul(nx, ptz));
    u64 pz = f2fma(phi.x, pty, f2mul(ny, ptx));
    rho.x = f2fma(a2, px, f2fma(NHALF, ptx, t.x));
    rho.y = f2fma(a2, py, f2fma(NHALF, pty, t.y));
    rho.z = f2fma(a2, pz, f2fma(NHALF, ptz, t.z));
}

// packed pose err; tp = 10 u64: [-t(3), qi(4), +q.xyz(3)]
__device__ __forceinline__ void pose_err2(const u64* tp, V2 at, Q2 aq,
                                          V2& rho, V2& phi) {
    const u64 TWO = C_TWO;
    V2 d{f2add(at.x, tp[0]), f2add(at.y, tp[1]), f2add(at.z, tp[2])};
    u64 qix = tp[3], qiy = tp[4], qiz = tp[5], qiw = tp[6];
    u64 nx = tp[7], ny = tp[8], nz = tp[9];
    u64 ux = f2fma(qiy, d.z, f2mul(nz, d.y)); ux = f2fma(qiw, d.x, ux);
    u64 uy = f2fma(qiz, d.x, f2mul(nx, d.z)); uy = f2fma(qiw, d.y, uy);
    u64 uz = f2fma(qix, d.y, f2mul(ny, d.x)); uz = f2fma(qiw, d.z, uz);
    u64 cx = f2fma(qiy, uz, f2mul(nz, uy));
    u64 cy = f2fma(qiz, ux, f2mul(nx, uz));
    u64 cz = f2fma(qix, uy, f2mul(ny, ux));
    V2 pe{f2fma(TWO, cx, d.x), f2fma(TWO, cy, d.y), f2fma(TWO, cz, d.z)};
    Q2 qe;
    qe.w = f2fma(nx, aq.x, f2fma(ny, aq.y, f2fma(nz, aq.z, f2mul(qiw, aq.w))));
    qe.x = f2fma(qiy, aq.z, f2fma(nz, aq.y, f2fma(qiw, aq.x, f2mul(qix, aq.w))));
    qe.y = f2fma(qiz, aq.x, f2fma(nx, aq.z, f2fma(qiw, aq.y, f2mul(qiy, aq.w))));
    qe.z = f2fma(qix, aq.y, f2fma(ny, aq.x, f2fma(qiw, aq.z, f2mul(qiz, aq.w))));
    se3_log2(pe, qe, rho, phi);
}

// packed SE3 accumulate: (t1,q1) <- (t1,q1) o (t2,q2)
__device__ __forceinline__ void se3_acc2(V2& t1, Q2& q1, V2 t2, Q2 q2) {
    const u64 NEG1 = C_NEG1, TWO = C_TWO;
    u64 nx = f2mul(q1.x, NEG1), ny = f2mul(q1.y, NEG1), nz = f2mul(q1.z, NEG1);
    u64 ux = f2fma(q1.y, t2.z, f2mul(nz, t2.y)); ux = f2fma(q1.w, t2.x, ux);
    u64 uy = f2fma(q1.z, t2.x, f2mul(nx, t2.z)); uy = f2fma(q1.w, t2.y, uy);
    u64 uz = f2fma(q1.x, t2.y, f2mul(ny, t2.x)); uz = f2fma(q1.w, t2.z, uz);
    u64 cx = f2fma(q1.y, uz, f2mul(nz, uy));
    u64 cy = f2fma(q1.z, ux, f2mul(nx, uz));
    u64 cz = f2fma(q1.x, uy, f2mul(ny, ux));
    t1.x = f2fma(TWO, cx, f2add(t1.x, t2.x));
    t1.y = f2fma(TWO, cy, f2add(t1.y, t2.y));
    t1.z = f2fma(TWO, cz, f2add(t1.z, t2.z));
    u64 w = f2fma(nx, q2.x, f2fma(ny, q2.y, f2fma(nz, q2.z, f2mul(q1.w, q2.w))));
    u64 x = f2fma(q1.y, q2.z, f2fma(nz, q2.y, f2fma(q1.w, q2.x, f2mul(q1.x, q2.w))));
    u64 y = f2fma(q1.z, q2.x, f2fma(nx, q2.z, f2fma(q1.w, q2.y, f2mul(q1.y, q2.w))));
    u64 z = f2fma(q1.x, q2.y, f2fma(ny, q2.x, f2fma(q1.w, q2.z, f2mul(q1.z, q2.w))));
    q1.x = x; q1.y = y; q1.z = z; q1.w = w;
}

// packed leaf lp: record = 6 ulonglong2: {otx,oty}{otz,oqx}{oqy,oqz}{oqw,Px}{Py,Pz}{Pw,pad}
__device__ __forceinline__ void leaf2(const ulonglong2* PR, int lp,
                                      float thA, float thB, V2& T, Q2& M) {
    const ulonglong2* r = PR + lp * 6;
    ulonglong2 r0 = r[0], r1 = r[1], r2 = r[2], r3 = r[3], r4 = r[4], r5 = r[5];
    float shA, chA, shB, chB;
    __sincosf(0.5f * thA, &shA, &chA);
    __sincosf(0.5f * thB, &shB, &chB);
    u64 sh = f2pack(shA, shB), ch = f2pack(chA, chB);
    T.x = r0.x; T.y = r0.y; T.z = r1.x;
    M.x = f2fma(sh, r3.y, f2mul(ch, r1.y));
    M.y = f2fma(sh, r4.x, f2mul(ch, r2.x));
    M.z = f2fma(sh, r4.y, f2mul(ch, r2.y));
    M.w = f2fma(sh, r5.x, f2mul(ch, r3.x));
}

__global__ void __launch_bounds__(TPB, 5)
ik_residual_kernel(const float* __restrict__ cfg,
                   const float* __restrict__ base,
                   const float* __restrict__ tgt,
                   const float* __restrict__ dbase,
                   const float* __restrict__ rest,
                   const float* __restrict__ joff,
                   const float* __restrict__ jaxis,
                   const float* __restrict__ jlo,
                   const float* __restrict__ jup,
                   float* __restrict__ out) {
    extern __shared__ __align__(16) float s[];

    const int t    = threadIdx.x;
    const int elem = t >> 1;        // 0..63
    const int seg  = t & 1;         // 0 -> joints 0-15, 1 -> joints 16-31
    const int e0   = blockIdx.x * EPB;

    // ---- stage: base (pad 8), cfg tile (-> S_OUT scratch), LIM, packed records/targets ----
    {
        const float* gb = base + (size_t)e0 * 7;
        #pragma unroll
        for (int i = t; i < EPB * 7; i += TPB) {
            int r = i / 7, c = i - r * 7;
            s[S_BASE + r * 8 + c] = gb[i];
        }
        const float4* gc = (const float4*)(cfg + (size_t)e0 * NJ);
        #pragma unroll
        for (int f = t; f < EPB * (NJ / 4); f += TPB) {
            int r = f >> 3, c = f & 7;
            *(float4*)(s + S_OUT + r * CFG_PAD + c * 4) = __ldg(gc + f);
        }
        if (t < 32) {   // limit/rest records
            s[S_LIM + t * 4 + 0] = __ldg(jup + t);
            s[S_LIM + t * 4 + 1] = __ldg(jlo + t);
            s[S_LIM + t * 4 + 2] = __ldg(rest + t);
            s[S_LIM + t * 4 + 3] = 0.0f;
        }
        if (t < 16) {   // packed leaf-pair records: pair (jA, jB) = (sp*16+i, sp*16+8+i)
            int sp = t >> 3, i = t & 7;
            int jA = sp * 16 + i, jB = jA + 8;
            float2* d = (float2*)(s + S_PREC) + t * 12;
            float vA[10], vB[10];
            #pragma unroll
            for (int u = 0; u < 2; u++) {
                int j = u ? jB : jA;
                float otx = __ldg(joff + j * 7 + 0), oty = __ldg(joff + j * 7 + 1);
                float otz = __ldg(joff + j * 7 + 2);
                float ox = __ldg(joff + j * 7 + 3), oy = __ldg(joff + j * 7 + 4);
                float oz = __ldg(joff + j * 7 + 5), ow = __ldg(joff + j * 7 + 6);
                float ax = __ldg(jaxis + j * 3 + 0), ay = __ldg(jaxis + j * 3 + 1);
                float az = __ldg(jaxis + j * 3 + 2);
                float* v = u ? vB : vA;
                v[0] = otx; v[1] = oty; v[2] = otz;
                v[3] = ox; v[4] = oy; v[5] = oz; v[6] = ow;
                v[7] = ow * ax + oy * az - oz * ay;
                v[8] = ow * ay + oz * ax - ox * az;
                v[9] = ow * az + ox * ay - oy * ax;
            }
            float PwA = -(vA[3] * __ldg(jaxis + jA * 3 + 0) + vA[4] * __ldg(jaxis + jA * 3 + 1) + vA[5] * __ldg(jaxis + jA * 3 + 2));
            float PwB = -(vB[3] * __ldg(jaxis + jB * 3 + 0) + vB[4] * __ldg(jaxis + jB * 3 + 1) + vB[5] * __ldg(jaxis + jB * 3 + 2));
            #pragma unroll
            for (int k = 0; k < 10; k++) d[k] = make_float2(vA[k], vB[k]);
            d[10] = make_float2(PwA, PwB);
            d[11] = make_float2(0.0f, 0.0f);
        }
        if (t >= 48 && t < 50) {   // packed target pairs (tgt 2p, 2p+1)
            int p = t - 48;
            const float* A = tgt + (2 * p) * 7;
            const float* Bp = tgt + (2 * p + 1) * 7;
            float2* d = (float2*)(s + S_TGT2) + p * 10;
            d[0] = make_float2(-__ldg(A + 0), -__ldg(Bp + 0));
            d[1] = make_float2(-__ldg(A + 1), -__ldg(Bp + 1));
            d[2] = make_float2(-__ldg(A + 2), -__ldg(Bp + 2));
            d[3] = make_float2(-__ldg(A + 3), -__ldg(Bp + 3));
            d[4] = make_float2(-__ldg(A + 4), -__ldg(Bp + 4));
            d[5] = make_float2(-__ldg(A + 5), -__ldg(Bp + 5));
            d[6] = make_float2( __ldg(A + 6),  __ldg(Bp + 6));
            d[7] = make_float2( __ldg(A + 3),  __ldg(Bp + 3));
            d[8] = make_float2( __ldg(A + 4),  __ldg(Bp + 4));
            d[9] = make_float2( __ldg(A + 5),  __ldg(Bp + 5));
        }
        if (t == 50) {   // scalar default base, padded 8
            s[S_DB + 0] = __ldg(dbase + 0); s[S_DB + 1] = __ldg(dbase + 1);
            s[S_DB + 2] = __ldg(dbase + 2); s[S_DB + 3] = 0.0f;
            s[S_DB + 4] = __ldg(dbase + 3); s[S_DB + 5] = __ldg(dbase + 4);
            s[S_DB + 6] = __ldg(dbase + 5); s[S_DB + 7] = __ldg(dbase + 6);
        }
    }
    __syncthreads();

    // own half of cfg row (16 angles)
    float th[16];
    {
        const float4* cr = (const float4*)(s + S_OUT + elem * CFG_PAD + seg * 16);
        #pragma unroll
        for (int i = 0; i < 4; i++) {
            float4 v = cr[i];
            th[4*i+0] = v.x; th[4*i+1] = v.y; th[4*i+2] = v.z; th[4*i+3] = v.w;
        }
    }
    // own base pose
    V bt; Q bq;
    {
        float4 b1 = *(const float4*)(s + S_BASE + elem * 8);
        float4 b2 = *(const float4*)(s + S_BASE + elem * 8 + 4);
        bt.x = b1.x; bt.y = b1.y; bt.z = b1.z;
        bq.x = b1.w; bq.y = b2.x; bq.z = b2.y; bq.w = b2.z;
    }
    __syncthreads();   // cfg scratch becomes output staging

    float* row = s + S_OUT + elem * OUTC;
    const ulonglong2* PR = (const ulonglong2*)(s + S_PREC);

    // ---- limit / rest residuals for this thread's 16 joints ----
    #pragma unroll
    for (int i = 0; i < 16; i += 2) {
        const int j = seg * 16 + i;
        float4 A  = *(const float4*)(s + S_LIM + j * 4);
        float4 Bv = *(const float4*)(s + S_LIM + (j + 1) * 4);
        float limA = fmaxf(th[i] - A.x, 0.0f)     + fminf(th[i] - A.y, 0.0f);
        float limB = fmaxf(th[i+1] - Bv.x, 0.0f)  + fminf(th[i+1] - Bv.y, 0.0f);
        *(float2*)(row + 24 + j) = make_float2(limA * 10.0f, limB * 10.0f);
        *(float2*)(row + 56 + j) = make_float2((th[i] - A.z) * 0.1f,
                                               (th[i+1] - Bv.z) * 0.1f);
    }

    // ---- ONE packed tree stream: lo = joints [seg*16, +8), hi = [seg*16+8, +8) ----
    V2 St, ta, tb, tc; Q2 Sq, qa, qb, qc;
    {
        const int b8 = seg * 8;
        leaf2(PR, b8 + 0, th[0], th[8],  St, Sq);
        leaf2(PR, b8 + 1, th[1], th[9],  ta, qa);
        se3_acc2(St, Sq, ta, qa);
        leaf2(PR, b8 + 2, th[2], th[10], ta, qa);
        leaf2(PR, b8 + 3, th[3], th[11], tb, qb);
        se3_acc2(ta, qa, tb, qb);
        se3_acc2(St, Sq, ta, qa);
        leaf2(PR, b8 + 4, th[4], th[12], tc, qc);
        leaf2(PR, b8 + 5, th[5], th[13], ta, qa);
        se3_acc2(tc, qc, ta, qa);
        leaf2(PR, b8 + 6, th[6], th[14], ta, qa);
        leaf2(PR, b8 + 7, th[7], th[15], tb, qb);
        se3_acc2(ta, qa, tb, qb);
        se3_acc2(tc, qc, ta, qa);
        se3_acc2(St, Sq, tc, qc);
    }

    // unpack: lo -> S1 (first 8 joints of my half), hi -> S2 (second 8)
    V S1, S2; Q s1q, s2q;
    f2unp(St.x, S1.x, S2.x); f2unp(St.y, S1.y, S2.y); f2unp(St.z, S1.z, S2.z);
    f2unp(Sq.x, s1q.x, s2q.x); f2unp(Sq.y, s1q.y, s2q.y);
    f2unp(Sq.z, s1q.z, s2q.z); f2unp(Sq.w, s1q.w, s2q.w);

    // E = S1 o S2 (16-joint product of my half)
    V Et; Q Eq;
    se3_comp(S1, s1q, S2, s2q, Et, Eq);

    // G = base o E (seg0: T16; seg1: discarded)
    V Gt; Q Gq;
    se3_comp(bt, bq, Et, Eq, Gt, Gq);

    // broadcast lane0's G (=T16) within the pair
    V Lt; Q Lq;
    Lt.x = __shfl_sync(0xffffffffu, Gt.x, 0, 2);
    Lt.y = __shfl_sync(0xffffffffu, Gt.y, 0, 2);
    Lt.z = __shfl_sync(0xffffffffu, Gt.z, 0, 2);
    Lq.x = __shfl_sync(0xffffffffu, Gq.x, 0, 2);
    Lq.y = __shfl_sync(0xffffffffu, Gq.y, 0, 2);
    Lq.z = __shfl_sync(0xffffffffu, Gq.z, 0, 2);
    Lq.w = __shfl_sync(0xffffffffu, Gq.w, 0, 2);

    // prefix select: seg0 -> base, seg1 -> T16
    V Pt; Q Pq;
    Pt.x = seg ? Lt.x : bt.x;  Pt.y = seg ? Lt.y : bt.y;  Pt.z = seg ? Lt.z : bt.z;
    Pq.x = seg ? Lq.x : bq.x;  Pq.y = seg ? Lq.y : bq.y;
    Pq.z = seg ? Lq.z : bq.z;  Pq.w = seg ? Lq.w : bq.w;

    // U1 = P o S1 (T8 / T24), U2 = P o E (T16 / T32)
    V U1t, U2t; Q U1q, U2q;
    se3_comp(Pt, Pq, S1, s1q, U1t, U1q);
    se3_comp(Pt, Pq, Et,  Eq,  U2t, U2q);

    // ---- PACKED pose residuals: (U1,U2) vs target pair seg ----
    {
        V2 at; Q2 aq;
        at.x = f2pack(U1t.x, U2t.x); at.y = f2pack(U1t.y, U2t.y); at.z = f2pack(U1t.z, U2t.z);
        aq.x = f2pack(U1q.x, U2q.x); aq.y = f2pack(U1q.y, U2q.y);
        aq.z = f2pack(U1q.z, U2q.z); aq.w = f2pack(U1q.w, U2q.w);
        V2 rho, phi;
        pose_err2((const u64*)(s + S_TGT2) + seg * 10, at, aq, rho, phi);
        const int kA = seg * 2, kB = seg * 2 + 1;
        float a0, b0, a1, b1, a2, b2, a3, b3, a4, b4, a5, b5;
        f2unp(rho.x, a0, b0); f2unp(rho.y, a1, b1); f2unp(rho.z, a2, b2);
        f2unp(phi.x, a3, b3); f2unp(phi.y, a4, b4); f2unp(phi.z, a5, b5);
        *(float2*)(row + kA * 6 + 0) = make_float2(a0, a1);
        *(float2*)(row + kA * 6 + 2) = make_float2(a2, 0.5f * a3);
        *(float2*)(row + kA * 6 + 4) = make_float2(0.5f * a4, 0.5f * a5);
        *(float2*)(row + kB * 6 + 0) = make_float2(b0, b1);
        *(float2*)(row + kB * 6 + 2) = make_float2(b2, 0.5f * b3);
        *(float2*)(row + kB * 6 + 4) = make_float2(0.5f * b4, 0.5f * b5);
    }

    // ---- base residuals: all 4 warps, lanes 0-15, one element each ----
    {
        const int lane = t & 31;
        const int w    = t >> 5;
        if (lane < 16) {
            const int el = w * 16 + lane;   // 0..63
            float4 b1 = *(const float4*)(s + S_BASE + el * 8);
            float4 b2 = *(const float4*)(s + S_BASE + el * 8 + 4);
            V rho, phi;
            pose_err_log(s + S_DB, V{b1.x, b1.y, b1.z},
                         Q{b1.w, b2.x, b2.y, b2.z}, rho, phi);
            float* r2 = s + S_OUT + el * OUTC;
            *(float2*)(r2 + 88) = make_float2(rho.x * 5.0f, rho.y * 5.0f);
            *(float2*)(r2 + 90) = make_float2(rho.z * 5.0f, phi.x * 5.0f);
            *(float2*)(r2 + 92) = make_float2(phi.y * 5.0f, phi.z * 5.0f);
        }
    }

    __syncthreads();

    // ---- flat vectorized flush: EPB*OUTC floats = 1504 float4 ----
    {
        float4* go4 = (float4*)(out + (size_t)e0 * OUTC);
        const float4* s4 = (const float4*)(s + S_OUT);
        for (int f = t; f < EPB * OUTC / 4; f += TPB) go4[f] = s4[f];
    }
}

extern "C" void kernel_launch(void* const* d_in, const int* in_sizes, int n_in,
                              void* d_out, int out_size) {
    const float* cfg   = (const float*)d_in[0];
    const float* base  = (const float*)d_in[1];
    const float* tgt   = (const float*)d_in[2];
    const float* dbase = (const float*)d_in[3];
    const float* rest  = (const float*)d_in[4];
    const float* joff  = (const float*)d_in[5];
    const float* jaxis = (const float*)d_in[6];
    const float* jlo   = (const float*)d_in[7];
    const float* jup   = (const float*)d_in[8];
    float* out = (float*)d_out;

    const int smem_bytes = S_TOTAL * sizeof(float);   // 28352
    cudaFuncSetAttribute(ik_residual_kernel,
                         cudaFuncAttributeMaxDynamicSharedMemorySize, smem_bytes);

    int B = in_sizes[0] / NJ;     // 65536
    int nblocks = B / EPB;        // 1024

    ik_residual_kernel<<<nblocks, TPB, smem_bytes>>>(cfg, base, tgt, dbase, rest,
                                                     joff, jaxis, jlo, jup, out);
}

// round 16
// speedup vs baseline: 1.0290x; 1.0290x over previous
#include <cuda_runtime.h>

#define NJ   32
#define TPB  128
#define EPB  32            // 32 elements per block, 4 threads (one per warp-seg) each
#define OUTC 94

typedef unsigned long long u64;

// ---- dynamic smem float offsets ----
#define S_OUT   0                       // 32*94 = 3008 (rows; cfg scratch early)
#define S_BASE  3008                    // 32 x 9 = 288 (pad 9: conflict-free)
#define S_LIM   3296                    // 32 x 4
#define S_TGTP  3424                    // 4 pair-records x 10 u64 = 80 floats
#define S_PREC  3504                    // 16 leaf-pair records x 12 u64 = 384
#define S_SP    3888                    // 128 products x 9 floats = 1152
#define S_TOTAL 5040                    // 20160 B

#define CFG_PAD 36

// ---- packed f32x2 primitives ----
__device__ __forceinline__ u64 f2pack(float lo, float hi) {
    u64 r;
    asm("mov.b64 %0, {%1, %2};" : "=l"(r)
        : "r"(__float_as_uint(lo)), "r"(__float_as_uint(hi)));
    return r;
}
__device__ __forceinline__ void f2unp(u64 a, float& lo, float& hi) {
    unsigned l, h;
    asm("mov.b64 {%0, %1}, %2;" : "=r"(l), "=r"(h) : "l"(a));
    lo = __uint_as_float(l); hi = __uint_as_float(h);
}
__device__ __forceinline__ u64 f2mul(u64 a, u64 b) {
    u64 r; asm("mul.rn.f32x2 %0, %1, %2;" : "=l"(r) : "l"(a), "l"(b)); return r;
}
__device__ __forceinline__ u64 f2add(u64 a, u64 b) {
    u64 r; asm("add.rn.f32x2 %0, %1, %2;" : "=l"(r) : "l"(a), "l"(b)); return r;
}
__device__ __forceinline__ u64 f2fma(u64 a, u64 b, u64 c) {
    u64 r; asm("fma.rn.f32x2 %0, %1, %2, %3;" : "=l"(r) : "l"(a), "l"(b), "l"(c)); return r;
}

#define C_NEG1  0xBF800000BF800000ULL
#define C_TWO   0x4000000040000000ULL
#define C_NHALF 0xBF000000BF000000ULL

struct Q { float x, y, z, w; };
struct V { float x, y, z; };
struct V2 { u64 x, y, z; };
struct Q2 { u64 x, y, z, w; };

// ================= scalar helpers =================
__device__ __forceinline__ V vcross(V a, V b) {
    return {a.y * b.z - a.z * b.y,
            a.z * b.x - a.x * b.z,
            a.x * b.y - a.y * b.x};
}
__device__ __forceinline__ V qrot(Q q, V t) {
    V v{q.x, q.y, q.z};
    V u = vcross(v, t);
    u.x = fmaf(q.w, t.x, u.x);
    u.y = fmaf(q.w, t.y, u.y);
    u.z = fmaf(q.w, t.z, u.z);
    V c = vcross(v, u);
    return {fmaf(2.0f, c.x, t.x), fmaf(2.0f, c.y, t.y), fmaf(2.0f, c.z, t.z)};
}
__device__ __forceinline__ Q qmul(Q a, Q b) {
    Q r;
    r.w = a.w * b.w - a.x * b.x - a.y * b.y - a.z * b.z;
    r.x = a.w * b.x + b.w * a.x + a.y * b.z - a.z * b.y;
    r.y = a.w * b.y + b.w * a.y + a.z * b.x - a.x * b.z;
    r.z = a.w * b.z + b.w * a.z + a.x * b.y - a.y * b.x;
    return r;
}
__device__ __forceinline__ void se3_comp(V t1, Q q1, V t2, Q q2, V& to, Q& qo) {
    V r = qrot(q1, t2);
    to.x = t1.x + r.x; to.y = t1.y + r.y; to.z = t1.z + r.z;
    qo = qmul(q1, q2);
}
__device__ __forceinline__ float atan2pos(float y, float x) {
    float mn = fminf(y, x), mx = fmaxf(y, x);
    float r  = __fdividef(mn, mx);
    float r2 = r * r;
    float p = fmaf(r2, -0.0117212f,  0.05265332f);
    p = fmaf(r2, p, -0.11643287f);
    p = fmaf(r2, p,  0.19354346f);
    p = fmaf(r2, p, -0.33262347f);
    p = fmaf(r2, p,  0.99997726f);
    float th = r * p;
    return (y > x) ? (1.57079632679489662f - th) : th;
}

// ================= packed helpers (validated R4/R13/R14) =================
__device__ __forceinline__ void log_scalars(float nv2, float qw,
                                            float& scale, float& a) {
    float nv  = sqrtf(fmaxf(nv2, 1e-14f));
    float qwc = fabsf(qw);
    float angle = 2.0f * atan2pos(nv, qwc);
    float wsafe = (qwc > 1e-8f) ? qwc : 1.0f;
    scale = (nv < 1e-6f) ? __fdividef(2.0f, wsafe) : __fdividef(angle, nv);
    float th2  = angle * angle;
    float abig = __fdividef(1.0f - 0.5f * scale * qwc, th2);
    a = (angle < 1e-4f) ? (1.0f / 12.0f + th2 * (1.0f / 720.0f)) : abig;
}

__device__ __forceinline__ void se3_log2(V2 t, Q2 q, V2& rho, V2& phi) {
    const u64 NEG1 = C_NEG1, NHALF = C_NHALF;
    float qwA, qwB; f2unp(q.w, qwA, qwB);
    u64 sg = f2pack(qwA < 0.0f ? -1.0f : 1.0f, qwB < 0.0f ? -1.0f : 1.0f);
    u64 qx = f2mul(q.x, sg), qy = f2mul(q.y, sg), qz = f2mul(q.z, sg);
    u64 nv2 = f2fma(qx, qx, f2fma(qy, qy, f2mul(qz, qz)));
    float n2A, n2B; f2unp(nv2, n2A, n2B);
    float scA, aA, scB, aB;
    log_scalars(n2A, qwA, scA, aA);
    log_scalars(n2B, qwB, scB, aB);
    u64 sc = f2pack(scA, scB), a2 = f2pack(aA, aB);
    phi.x = f2mul(qx, sc); phi.y = f2mul(qy, sc); phi.z = f2mul(qz, sc);
    u64 nx = f2mul(phi.x, NEG1), ny = f2mul(phi.y, NEG1), nz = f2mul(phi.z, NEG1);
    u64 ptx = f2fma(phi.y, t.z, f2mul(nz, t.y));
    u64 pty = f2fma(phi.z, t.x, f2mul(nx, t.z));
    u64 ptz = f2fma(phi.x, t.y, f2mul(ny, t.x));
    u64 px = f2fma(phi.y, ptz, f2mul(nz, pty));
    u64 py = f2fma(phi.z, ptx, f2mul(nx, ptz));
    u64 pz = f2fma(phi.x, pty, f2mul(ny, ptx));
    rho.x = f2fma(a2, px, f2fma(NHALF, ptx, t.x));
    rho.y = f2fma(a2, py, f2fma(NHALF, pty, t.y));
    rho.z = f2fma(a2, pz, f2fma(NHALF, ptz, t.z));
}

// packed pose err; tp = 10 u64: [-t(3), qi(4), +q.xyz(3)]
__device__ __forceinline__ void pose_err2(const u64* tp, V2 at, Q2 aq,
                                          V2& rho, V2& phi) {
    const u64 TWO = C_TWO;
    V2 d{f2add(at.x, tp[0]), f2add(at.y, tp[1]), f2add(at.z, tp[2])};
    u64 qix = tp[3], qiy = tp[4], qiz = tp[5], qiw = tp[6];
    u64 nx = tp[7], ny = tp[8], nz = tp[9];
    u64 ux = f2fma(qiy, d.z, f2mul(nz, d.y)); ux = f2fma(qiw, d.x, ux);
    u64 uy = f2fma(qiz, d.x, f2mul(nx, d.z)); uy = f2fma(qiw, d.y, uy);
    u64 uz = f2fma(qix, d.y, f2mul(ny, d.x)); uz = f2fma(qiw, d.z, uz);
    u64 cx = f2fma(qiy, uz, f2mul(nz, uy));
    u64 cy = f2fma(qiz, ux, f2mul(nx, uz));
    u64 cz = f2fma(qix, uy, f2mul(ny, ux));
    V2 pe{f2fma(TWO, cx, d.x), f2fma(TWO, cy, d.y), f2fma(TWO, cz, d.z)};
    Q2 qe;
    qe.w = f2fma(nx, aq.x, f2fma(ny, aq.y, f2fma(nz, aq.z, f2mul(qiw, aq.w))));
    qe.x = f2fma(qiy, aq.z, f2fma(nz, aq.y, f2fma(qiw, aq.x, f2mul(qix, aq.w))));
    qe.y = f2fma(qiz, aq.x, f2fma(nx, aq.z, f2fma(qiw, aq.y, f2mul(qiy, aq.w))));
    qe.z = f2fma(qix, aq.y, f2fma(ny, aq.x, f2fma(qiw, aq.z, f2mul(qiz, aq.w))));
    se3_log2(pe, qe, rho, phi);
}

// packed SE3 accumulate: (t1,q1) <- (t1,q1) o (t2,q2)
__device__ __forceinline__ void se3_acc2(V2& t1, Q2& q1, V2 t2, Q2 q2) {
    const u64 NEG1 = C_NEG1, TWO = C_TWO;
    u64 nx = f2mul(q1.x, NEG1), ny = f2mul(q1.y, NEG1), nz = f2mul(q1.z, NEG1);
    u64 ux = f2fma(q1.y, t2.z, f2mul(nz, t2.y)); ux = f2fma(q1.w, t2.x, ux);
    u64 uy = f2fma(q1.z, t2.x, f2mul(nx, t2.z)); uy = f2fma(q1.w, t2.y, uy);
    u64 uz = f2fma(q1.x, t2.y, f2mul(ny, t2.x)); uz = f2fma(q1.w, t2.z, uz);
    u64 cx = f2fma(q1.y, uz, f2mul(nz, uy));
    u64 cy = f2fma(q1.z, ux, f2mul(nx, uz));
    u64 cz = f2fma(q1.x, uy, f2mul(ny, ux));
    t1.x = f2fma(TWO, cx, f2add(t1.x, t2.x));
    t1.y = f2fma(TWO, cy, f2add(t1.y, t2.y));
    t1.z = f2fma(TWO, cz, f2add(t1.z, t2.z));
    u64 w = f2fma(nx, q2.x, f2fma(ny, q2.y, f2fma(nz, q2.z, f2mul(q1.w, q2.w))));
    u64 x = f2fma(q1.y, q2.z, f2fma(nz, q2.y, f2fma(q1.w, q2.x, f2mul(q1.x, q2.w))));
    u64 y = f2fma(q1.z, q2.x, f2fma(nx, q2.z, f2fma(q1.w, q2.y, f2mul(q1.y, q2.w))));
    u64 z = f2fma(q1.x, q2.y, f2fma(ny, q2.x, f2fma(q1.w, q2.z, f2mul(q1.z, q2.w))));
    q1.x = x; q1.y = y; q1.z = z; q1.w = w;
}

// packed leaf lp (warp-uniform broadcast LDS):
// record = 6 ulonglong2: {otx,oty}{otz,oqx}{oqy,oqz}{oqw,Px}{Py,Pz}{Pw,pad}
__device__ __forceinline__ void leaf2(const ulonglong2* PR, int lp,
                                      float thA, float thB, V2& T, Q2& M) {
    const ulonglong2* r = PR + lp * 6;
    ulonglong2 r0 = r[0], r1 = r[1], r2 = r[2], r3 = r[3], r4 = r[4], r5 = r[5];
    float shA, chA, shB, chB;
    __sincosf(0.5f * thA, &shA, &chA);
    __sincosf(0.5f * thB, &shB, &chB);
    u64 sh = f2pack(shA, shB), ch = f2pack(chA, chB);
    T.x = r0.x; T.y = r0.y; T.z = r1.x;
    M.x = f2fma(sh, r3.y, f2mul(ch, r1.y));
    M.y = f2fma(sh, r4.x, f2mul(ch, r2.x));
    M.z = f2fma(sh, r4.y, f2mul(ch, r2.y));
    M.w = f2fma(sh, r5.x, f2mul(ch, r3.x));
}

__global__ void __launch_bounds__(TPB, 6)
ik_residual_kernel(const float* __restrict__ cfg,
                   const float* __restrict__ base,
                   const float* __restrict__ tgt,
                   const float* __restrict__ dbase,
                   const float* __restrict__ rest,
                   const float* __restrict__ joff,
                   const float* __restrict__ jaxis,
                   const float* __restrict__ jlo,
                   const float* __restrict__ jup,
                   float* __restrict__ out) {
    extern __shared__ __align__(16) float s[];

    const int t  = threadIdx.x;
    const int w  = t >> 5;      // warp = segment 0..3 (joints [8w, 8w+8))
    const int l  = t & 31;      // lane = element 0..31
    const int e0 = blockIdx.x * EPB;

    // ---- stage: base (stride 9), cfg tile (-> S_OUT scratch), LIM, records, targets ----
    {
        const float* gb = base + (size_t)e0 * 7;
        #pragma unroll
        for (int i = t; i < EPB * 7; i += TPB) {
            int r = i / 7, c = i - r * 7;
            s[S_BASE + r * 9 + c] = gb[i];
        }
        const float4* gc = (const float4*)(cfg + (size_t)e0 * NJ);
        #pragma unroll
        for (int f = t; f < EPB * (NJ / 4); f += TPB) {
            int r = f >> 3, c = f & 7;
            *(float4*)(s + S_OUT + r * CFG_PAD + c * 4) = __ldg(gc + f);
        }
        if (t < 32) {   // limit/rest records
            s[S_LIM + t * 4 + 0] = __ldg(jup + t);
            s[S_LIM + t * 4 + 1] = __ldg(jlo + t);
            s[S_LIM + t * 4 + 2] = __ldg(rest + t);
            s[S_LIM + t * 4 + 3] = 0.0f;
        }
        if (t < 16) {   // leaf-pair records: seg ws = t>>2, i = t&3 -> (8ws+i, 8ws+i+4)
            int ws = t >> 2, i = t & 3;
            int jA = 8 * ws + i, jB = jA + 4;
            float2* d = (float2*)(s + S_PREC) + t * 12;
            float vA[10], vB[10];
            #pragma unroll
            for (int u = 0; u < 2; u++) {
                int j = u ? jB : jA;
                float otx = __ldg(joff + j * 7 + 0), oty = __ldg(joff + j * 7 + 1);
                float otz = __ldg(joff + j * 7 + 2);
                float ox = __ldg(joff + j * 7 + 3), oy = __ldg(joff + j * 7 + 4);
                float oz = __ldg(joff + j * 7 + 5), ow = __ldg(joff + j * 7 + 6);
                float ax = __ldg(jaxis + j * 3 + 0), ay = __ldg(jaxis + j * 3 + 1);
                float az = __ldg(jaxis + j * 3 + 2);
                float* v = u ? vB : vA;
                v[0] = otx; v[1] = oty; v[2] = otz;
                v[3] = ox; v[4] = oy; v[5] = oz; v[6] = ow;
                v[7] = ow * ax + oy * az - oz * ay;
                v[8] = ow * ay + oz * ax - ox * az;
                v[9] = ow * az + ox * ay - oy * ax;
            }
            float PwA = -(vA[3] * __ldg(jaxis + jA * 3 + 0) + vA[4] * __ldg(jaxis + jA * 3 + 1) + vA[5] * __ldg(jaxis + jA * 3 + 2));
            float PwB = -(vB[3] * __ldg(jaxis + jB * 3 + 0) + vB[4] * __ldg(jaxis + jB * 3 + 1) + vB[5] * __ldg(jaxis + jB * 3 + 2));
            #pragma unroll
            for (int k = 0; k < 10; k++) d[k] = make_float2(vA[k], vB[k]);
            d[10] = make_float2(PwA, PwB);
            d[11] = make_float2(0.0f, 0.0f);
        }
        if (t >= 16 && t < 20) {   // pair-target records: (tgt_w | dbase)
            int ws = t - 16;
            const float* A = tgt + ws * 7;
            const float* Bp = dbase;
            float2* d = (float2*)(s + S_TGTP) + ws * 10;
            d[0] = make_float2(-__ldg(A + 0), -__ldg(Bp + 0));
            d[1] = make_float2(-__ldg(A + 1), -__ldg(Bp + 1));
            d[2] = make_float2(-__ldg(A + 2), -__ldg(Bp + 2));
            d[3] = make_float2(-__ldg(A + 3), -__ldg(Bp + 3));
            d[4] = make_float2(-__ldg(A + 4), -__ldg(Bp + 4));
            d[5] = make_float2(-__ldg(A + 5), -__ldg(Bp + 5));
            d[6] = make_float2( __ldg(A + 6),  __ldg(Bp + 6));
            d[7] = make_float2( __ldg(A + 3),  __ldg(Bp + 3));
            d[8] = make_float2( __ldg(A + 4),  __ldg(Bp + 4));
            d[9] = make_float2( __ldg(A + 5),  __ldg(Bp + 5));
        }
    }
    __syncthreads();

    // own 8 joint angles (element l, joints [8w, 8w+8))
    float th[8];
    {
        const float4* cr = (const float4*)(s + S_OUT + l * CFG_PAD + w * 8);
        float4 v0 = cr[0], v1 = cr[1];
        th[0] = v0.x; th[1] = v0.y; th[2] = v0.z; th[3] = v0.w;
        th[4] = v1.x; th[5] = v1.y; th[6] = v1.z; th[7] = v1.w;
    }
    // own base pose (element l)
    V bt; Q bq;
    {
        const float* bp = s + S_BASE + l * 9;
        bt.x = bp[0]; bt.y = bp[1]; bt.z = bp[2];
        bq.x = bp[3]; bq.y = bp[4]; bq.z = bp[5]; bq.w = bp[6];
    }
    __syncthreads();   // cfg scratch becomes output rows

    float* row = s + S_OUT + l * OUTC;
    const ulonglong2* PR = (const ulonglong2*)(s + S_PREC);

    // ---- limit / rest residuals for my 8 joints (LIM reads are broadcasts) ----
    #pragma unroll
    for (int i = 0; i < 8; i += 2) {
        const int j = 8 * w + i;
        float4 A  = *(const float4*)(s + S_LIM + j * 4);
        float4 Bv = *(const float4*)(s + S_LIM + (j + 1) * 4);
        float limA = fmaxf(th[i] - A.x, 0.0f)     + fminf(th[i] - A.y, 0.0f);
        float limB = fmaxf(th[i+1] - Bv.x, 0.0f)  + fminf(th[i+1] - Bv.y, 0.0f);
        *(float2*)(row + 24 + j) = make_float2(limA * 10.0f, limB * 10.0f);
        *(float2*)(row + 56 + j) = make_float2((th[i] - A.z) * 0.1f,
                                               (th[i+1] - Bv.z) * 0.1f);
    }

    // ---- packed 8-joint product: lo = joints (8w+0..3 chain), hi = (8w+4..7) ----
    V Sv; Q Sq_s;
    {
        const int lp0 = w * 4;
        V2 St, ta, tb, tc; Q2 Sq, qa, qb, qc;
        leaf2(PR, lp0 + 0, th[0], th[4], St, Sq);
        leaf2(PR, lp0 + 1, th[1], th[5], ta, qa);
        se3_acc2(St, Sq, ta, qa);                 // (X0X1 | X4X5)
        leaf2(PR, lp0 + 2, th[2], th[6], tb, qb);
        leaf2(PR, lp0 + 3, th[3], th[7], tc, qc);
        se3_acc2(tb, qb, tc, qc);                 // (X2X3 | X6X7)
        se3_acc2(St, Sq, tb, qb);                 // (X0..X3 | X4..X7)

        V A1, B1; Q A1q, B1q;
        f2unp(St.x, A1.x, B1.x); f2unp(St.y, A1.y, B1.y); f2unp(St.z, A1.z, B1.z);
        f2unp(Sq.x, A1q.x, B1q.x); f2unp(Sq.y, A1q.y, B1q.y);
        f2unp(Sq.z, A1q.z, B1q.z); f2unp(Sq.w, A1q.w, B1q.w);
        se3_comp(A1, A1q, B1, B1q, Sv, Sq_s);     // full 8-joint product
    }

    // ---- exchange products through smem (stride 9 -> conflict-free) ----
    {
        float* sp = s + S_SP + (w * 32 + l) * 9;
        sp[0] = Sv.x; sp[1] = Sv.y; sp[2] = Sv.z;
        sp[3] = Sq_s.x; sp[4] = Sq_s.y; sp[5] = Sq_s.z; sp[6] = Sq_s.w;
    }
    __syncthreads();

    // ---- per-warp prefix: P = base o S0 o ... o S_{w-1}; T = P o S_own ----
    V Pt = bt; Q Pq = bq;
    for (int k = 0; k < w; k++) {            // warp-uniform trip count
        const float* sp = s + S_SP + (k * 32 + l) * 9;
        V kt{sp[0], sp[1], sp[2]};
        Q kq{sp[3], sp[4], sp[5], sp[6]};
        V nt; Q nq;
        se3_comp(Pt, Pq, kt, kq, nt, nq);
        Pt = nt; Pq = nq;
    }
    V Tt; Q Tq;
    se3_comp(Pt, Pq, Sv, Sq_s, Tt, Tq);      // pose at link 8(w+1)

    // ---- ONE packed pose log: lo = (T vs tgt_w), hi = (base vs dbase) ----
    {
        V2 at; Q2 aq;
        at.x = f2pack(Tt.x, bt.x); at.y = f2pack(Tt.y, bt.y); at.z = f2pack(Tt.z, bt.z);
        aq.x = f2pack(Tq.x, bq.x); aq.y = f2pack(Tq.y, bq.y);
        aq.z = f2pack(Tq.z, bq.z); aq.w = f2pack(Tq.w, bq.w);
        V2 rho, phi;
        pose_err2((const u64*)(s + S_TGTP) + w * 10, at, aq, rho, phi);
        float a0, b0, a1, b1, a2, b2, a3, b3, a4, b4, a5, b5;
        f2unp(rho.x, a0, b0); f2unp(rho.y, a1, b1); f2unp(rho.z, a2, b2);
        f2unp(phi.x, a3, b3); f2unp(phi.y, a4, b4); f2unp(phi.z, a5, b5);
        *(float2*)(row + w * 6 + 0) = make_float2(a0, a1);
        *(float2*)(row + w * 6 + 2) = make_float2(a2, 0.5f * a3);
        *(float2*)(row + w * 6 + 4) = make_float2(0.5f * a4, 0.5f * a5);
        if (w == 0) {   // warp-uniform branch: base residual from hi lane
            *(float2*)(row + 88) = make_float2(b0 * 5.0f, b1 * 5.0f);
            *(float2*)(row + 90) = make_float2(b2 * 5.0f, b3 * 5.0f);
            *(float2*)(row + 92) = make_float2(b4 * 5.0f, b5 * 5.0f);
        }
    }

    __syncthreads();

    // ---- flat vectorized flush: EPB*OUTC = 3008 floats = 752 float4 ----
    {
        float4* go4 = (float4*)(out + (size_t)e0 * OUTC);
        const float4* s4 = (const float4*)(s + S_OUT);
        for (int f = t; f < EPB * OUTC / 4; f += TPB) go4[f] = s4[f];
    }
}

extern "C" void kernel_launch(void* const* d_in, const int* in_sizes, int n_in,
                              void* d_out, int out_size) {
    const float* cfg   = (const float*)d_in[0];
    const float* base  = (const float*)d_in[1];
    const float* tgt   = (const float*)d_in[2];
    const float* dbase = (const float*)d_in[3];
    const float* rest  = (const float*)d_in[4];
    const float* joff  = (const float*)d_in[5];
    const float* jaxis = (const float*)d_in[6];
    const float* jlo   = (const float*)d_in[7];
    const float* jup   = (const float*)d_in[8];
    float* out = (float*)d_out;

    const int smem_bytes = S_TOTAL * sizeof(float);   // 20160
    cudaFuncSetAttribute(ik_residual_kernel,
                         cudaFuncAttributeMaxDynamicSharedMemorySize, smem_bytes);

    int B = in_sizes[0] / NJ;     // 65536
    int nblocks = B / EPB;        // 2048

    ik_residual_kernel<<<nblocks, TPB, smem_bytes>>>(cfg, base, tgt, dbase, rest,
                                                     joff, jaxis, jlo, jup, out);
}

// round 17
// speedup vs baseline: 1.0713x; 1.0410x over previous
#include <cuda_runtime.h>

#define NJ   32
#define TPB  128
#define EPB  (TPB / 2)     // 64 elements per block, 2 threads each
#define OUTC 94

typedef unsigned long long u64;

// ---- dynamic smem float offsets ----
#define S_OUT   0                       // 64*94 = 6016 output rows
#define S_CFG   6016                    // 64 x 33 = 2112 (stride 33: conflict-free)
#define S_BASE  8128                    // 64 x 9 = 576 (stride 9: conflict-free)
#define S_LIM   8704                    // 32 x 4
#define S_DB    8832                    // 8 (scalar default-base, padded, 16B aligned)
#define S_TGT2  8840                    // 2 pairs x 10 u64 = 40 floats (8B aligned)
#define S_PREC  8920                    // 16 leaf-pairs x 12 u64 = 384 (16B aligned)
#define S_TOTAL 9304                    // 37216 B

// ---- packed f32x2 primitives ----
__device__ __forceinline__ u64 f2pack(float lo, float hi) {
    u64 r;
    asm("mov.b64 %0, {%1, %2};" : "=l"(r)
        : "r"(__float_as_uint(lo)), "r"(__float_as_uint(hi)));
    return r;
}
__device__ __forceinline__ void f2unp(u64 a, float& lo, float& hi) {
    unsigned l, h;
    asm("mov.b64 {%0, %1}, %2;" : "=r"(l), "=r"(h) : "l"(a));
    lo = __uint_as_float(l); hi = __uint_as_float(h);
}
__device__ __forceinline__ u64 f2mul(u64 a, u64 b) {
    u64 r; asm("mul.rn.f32x2 %0, %1, %2;" : "=l"(r) : "l"(a), "l"(b)); return r;
}
__device__ __forceinline__ u64 f2add(u64 a, u64 b) {
    u64 r; asm("add.rn.f32x2 %0, %1, %2;" : "=l"(r) : "l"(a), "l"(b)); return r;
}
__device__ __forceinline__ u64 f2fma(u64 a, u64 b, u64 c) {
    u64 r; asm("fma.rn.f32x2 %0, %1, %2, %3;" : "=l"(r) : "l"(a), "l"(b), "l"(c)); return r;
}

#define C_NEG1  0xBF800000BF800000ULL
#define C_TWO   0x4000000040000000ULL
#define C_NHALF 0xBF000000BF000000ULL

struct Q { float x, y, z, w; };
struct V { float x, y, z; };
struct V2 { u64 x, y, z; };
struct Q2 { u64 x, y, z, w; };

// ================= scalar helpers =================
__device__ __forceinline__ V vcross(V a, V b) {
    return {a.y * b.z - a.z * b.y,
            a.z * b.x - a.x * b.z,
            a.x * b.y - a.y * b.x};
}
__device__ __forceinline__ V qrot(Q q, V t) {
    V v{q.x, q.y, q.z};
    V u = vcross(v, t);
    u.x = fmaf(q.w, t.x, u.x);
    u.y = fmaf(q.w, t.y, u.y);
    u.z = fmaf(q.w, t.z, u.z);
    V c = vcross(v, u);
    return {fmaf(2.0f, c.x, t.x), fmaf(2.0f, c.y, t.y), fmaf(2.0f, c.z, t.z)};
}
__device__ __forceinline__ Q qmul(Q a, Q b) {
    Q r;
    r.w = a.w * b.w - a.x * b.x - a.y * b.y - a.z * b.z;
    r.x = a.w * b.x + b.w * a.x + a.y * b.z - a.z * b.y;
    r.y = a.w * b.y + b.w * a.y + a.z * b.x - a.x * b.z;
    r.z = a.w * b.z + b.w * a.z + a.x * b.y - a.y * b.x;
    return r;
}
__device__ __forceinline__ void se3_comp(V t1, Q q1, V t2, Q q2, V& to, Q& qo) {
    V r = qrot(q1, t2);
    to.x = t1.x + r.x; to.y = t1.y + r.y; to.z = t1.z + r.z;
    qo = qmul(q1, q2);
}
__device__ __forceinline__ float atan2pos(float y, float x) {
    float mn = fminf(y, x), mx = fmaxf(y, x);
    float r  = __fdividef(mn, mx);
    float r2 = r * r;
    float p = fmaf(r2, -0.0117212f,  0.05265332f);
    p = fmaf(r2, p, -0.11643287f);
    p = fmaf(r2, p,  0.19354346f);
    p = fmaf(r2, p, -0.33262347f);
    p = fmaf(r2, p,  0.99997726f);
    float th = r * p;
    return (y > x) ? (1.57079632679489662f - th) : th;
}
__device__ __forceinline__ void se3_log(V t, Q q, V& rho, V& phi) {
    float sgn = (q.w < 0.0f) ? -1.0f : 1.0f;
    float qx = q.x * sgn, qy = q.y * sgn, qz = q.z * sgn, qw = q.w * sgn;
    float nv2 = qx * qx + qy * qy + qz * qz;
    float nv  = sqrtf(fmaxf(nv2, 1e-14f));
    float angle = 2.0f * atan2pos(nv, qw);
    float wsafe = (fabsf(qw) > 1e-8f) ? qw : 1.0f;
    float scale = (nv < 1e-6f) ? __fdividef(2.0f, wsafe) : __fdividef(angle, nv);
    phi = {qx * scale, qy * scale, qz * scale};
    float th2 = angle * angle;
    float abig = __fdividef(1.0f - 0.5f * scale * qw, th2);
    float a = (angle < 1e-4f) ? (1.0f / 12.0f + th2 * (1.0f / 720.0f)) : abig;
    V pt  = vcross(phi, t);
    V ppt = vcross(phi, pt);
    rho = {t.x - 0.5f * pt.x + a * ppt.x,
           t.y - 0.5f * pt.y + a * ppt.y,
           t.z - 0.5f * pt.z + a * ppt.z};
}
__device__ __forceinline__ void pose_err_log(const float* tp, V at, Q aq,
                                             V& rho, V& phi) {
    float4 a = *(const float4*)tp;
    float4 b = *(const float4*)(tp + 4);
    Q qi{-b.x, -b.y, -b.z, b.w};
    V d{at.x - a.x, at.y - a.y, at.z - a.z};
    V pe = qrot(qi, d);
    Q qe = qmul(qi, aq);
    se3_log(pe, qe, rho, phi);
}

// ================= packed helpers (validated R4/R13/R14/R15) =================
__device__ __forceinline__ void log_scalars(float nv2, float qw,
                                            float& scale, float& a) {
    float nv  = sqrtf(fmaxf(nv2, 1e-14f));
    float qwc = fabsf(qw);
    float angle = 2.0f * atan2pos(nv, qwc);
    float wsafe = (qwc > 1e-8f) ? qwc : 1.0f;
    scale = (nv < 1e-6f) ? __fdividef(2.0f, wsafe) : __fdividef(angle, nv);
    float th2  = angle * angle;
    float abig = __fdividef(1.0f - 0.5f * scale * qwc, th2);
    a = (angle < 1e-4f) ? (1.0f / 12.0f + th2 * (1.0f / 720.0f)) : abig;
}

__device__ __forceinline__ void se3_log2(V2 t, Q2 q, V2& rho, V2& phi) {
    const u64 NEG1 = C_NEG1, NHALF = C_NHALF;
    float qwA, qwB; f2unp(q.w, qwA, qwB);
    u64 sg = f2pack(qwA < 0.0f ? -1.0f : 1.0f, qwB < 0.0f ? -1.0f : 1.0f);
    u64 qx = f2mul(q.x, sg), qy = f2mul(q.y, sg), qz = f2mul(q.z, sg);
    u64 nv2 = f2fma(qx, qx, f2fma(qy, qy, f2mul(qz, qz)));
    float n2A, n2B; f2unp(nv2, n2A, n2B);
    float scA, aA, scB, aB;
    log_scalars(n2A, qwA, scA, aA);
    log_scalars(n2B, qwB, scB, aB);
    u64 sc = f2pack(scA, scB), a2 = f2pack(aA, aB);
    phi.x = f2mul(qx, sc); phi.y = f2mul(qy, sc); phi.z = f2mul(qz, sc);
    u64 nx = f2mul(phi.x, NEG1), ny = f2mul(phi.y, NEG1), nz = f2mul(phi.z, NEG1);
    u64 ptx = f2fma(phi.y, t.z, f2mul(nz, t.y));
    u64 pty = f2fma(phi.z, t.x, f2mul(nx, t.z));
    u64 ptz = f2fma(phi.x, t.y, f2mul(ny, t.x));
    u64 px = f2fma(phi.y, ptz, f2mul(nz, pty));
    u64 py = f2fma(phi.z, ptx, f2mul(nx, ptz));
    u64 pz = f2fma(phi.x, pty, f2mul(ny, ptx));
    rho.x = f2fma(a2, px, f2fma(NHALF, ptx, t.x));
    rho.y = f2fma(a2, py, f2fma(NHALF, pty, t.y));
    rho.z = f2fma(a2, pz, f2fma(NHALF, ptz, t.z));
}

// packed pose err; tp = 10 u64: [-t(3), qi(4), +q.xyz(3)]
__device__ __forceinline__ void pose_err2(const u64* tp, V2 at, Q2 aq,
                                          V2& rho, V2& phi) {
    const u64 TWO = C_TWO;
    V2 d{f2add(at.x, tp[0]), f2add(at.y, tp[1]), f2add(at.z, tp[2])};
    u64 qix = tp[3], qiy = tp[4], qiz = tp[5], qiw = tp[6];
    u64 nx = tp[7], ny = tp[8], nz = tp[9];
    u64 ux = f2fma(qiy, d.z, f2mul(nz, d.y)); ux = f2fma(qiw, d.x, ux);
    u64 uy = f2fma(qiz, d.x, f2mul(nx, d.z)); uy = f2fma(qiw, d.y, uy);
    u64 uz = f2fma(qix, d.y, f2mul(ny, d.x)); uz = f2fma(qiw, d.z, uz);
    u64 cx = f2fma(qiy, uz, f2mul(nz, uy));
    u64 cy = f2fma(qiz, ux, f2mul(nx, uz));
    u64 cz = f2fma(qix, uy, f2mul(ny, ux));
    V2 pe{f2fma(TWO, cx, d.x), f2fma(TWO, cy, d.y), f2fma(TWO, cz, d.z)};
    Q2 qe;
    qe.w = f2fma(nx, aq.x, f2fma(ny, aq.y, f2fma(nz, aq.z, f2mul(qiw, aq.w))));
    qe.x = f2fma(qiy, aq.z, f2fma(nz, aq.y, f2fma(qiw, aq.x, f2mul(qix, aq.w))));
    qe.y = f2fma(qiz, aq.x, f2fma(nx, aq.z, f2fma(qiw, aq.y, f2mul(qiy, aq.w))));
    qe.z = f2fma(qix, aq.y, f2fma(ny, aq.x, f2fma(qiw, aq.z, f2mul(qiz, aq.w))));
    se3_log2(pe, qe, rho, phi);
}

// packed SE3 accumulate: (t1,q1) <- (t1,q1) o (t2,q2)
__device__ __forceinline__ void se3_acc2(V2& t1, Q2& q1, V2 t2, Q2 q2) {
    const u64 NEG1 = C_NEG1, TWO = C_TWO;
    u64 nx = f2mul(q1.x, NEG1), ny = f2mul(q1.y, NEG1), nz = f2mul(q1.z, NEG1);
    u64 ux = f2fma(q1.y, t2.z, f2mul(nz, t2.y)); ux = f2fma(q1.w, t2.x, ux);
    u64 uy = f2fma(q1.z, t2.x, f2mul(nx, t2.z)); uy = f2fma(q1.w, t2.y, uy);
    u64 uz = f2fma(q1.x, t2.y, f2mul(ny, t2.x)); uz = f2fma(q1.w, t2.z, uz);
    u64 cx = f2fma(q1.y, uz, f2mul(nz, uy));
    u64 cy = f2fma(q1.z, ux, f2mul(nx, uz));
    u64 cz = f2fma(q1.x, uy, f2mul(ny, ux));
    t1.x = f2fma(TWO, cx, f2add(t1.x, t2.x));
    t1.y = f2fma(TWO, cy, f2add(t1.y, t2.y));
    t1.z = f2fma(TWO, cz, f2add(t1.z, t2.z));
    u64 w = f2fma(nx, q2.x, f2fma(ny, q2.y, f2fma(nz, q2.z, f2mul(q1.w, q2.w))));
    u64 x = f2fma(q1.y, q2.z, f2fma(nz, q2.y, f2fma(q1.w, q2.x, f2mul(q1.x, q2.w))));
    u64 y = f2fma(q1.z, q2.x, f2fma(nx, q2.z, f2fma(q1.w, q2.y, f2mul(q1.y, q2.w))));
    u64 z = f2fma(q1.x, q2.y, f2fma(ny, q2.x, f2fma(q1.w, q2.z, f2mul(q1.z, q2.w))));
    q1.x = x; q1.y = y; q1.z = z; q1.w = w;
}

// packed leaf lp: record = 6 ulonglong2: {otx,oty}{otz,oqx}{oqy,oqz}{oqw,Px}{Py,Pz}{Pw,pad}
__device__ __forceinline__ void leaf2(const ulonglong2* PR, int lp,
                                      float thA, float thB, V2& T, Q2& M) {
    const ulonglong2* r = PR + lp * 6;
    ulonglong2 r0 = r[0], r1 = r[1], r2 = r[2], r3 = r[3], r4 = r[4], r5 = r[5];
    float shA, chA, shB, chB;
    __sincosf(0.5f * thA, &shA, &chA);
    __sincosf(0.5f * thB, &shB, &chB);
    u64 sh = f2pack(shA, shB), ch = f2pack(chA, chB);
    T.x = r0.x; T.y = r0.y; T.z = r1.x;
    M.x = f2fma(sh, r3.y, f2mul(ch, r1.y));
    M.y = f2fma(sh, r4.x, f2mul(ch, r2.x));
    M.z = f2fma(sh, r4.y, f2mul(ch, r2.y));
    M.w = f2fma(sh, r5.x, f2mul(ch, r3.x));
}

__global__ void __launch_bounds__(TPB, 6)
ik_residual_kernel(const float* __restrict__ cfg,
                   const float* __restrict__ base,
                   const float* __restrict__ tgt,
                   const float* __restrict__ dbase,
                   const float* __restrict__ rest,
                   const float* __restrict__ joff,
                   const float* __restrict__ jaxis,
                   const float* __restrict__ jlo,
                   const float* __restrict__ jup,
                   float* __restrict__ out) {
    extern __shared__ __align__(16) float s[];

    const int t    = threadIdx.x;
    const int elem = t >> 1;        // 0..63
    const int seg  = t & 1;         // 0 -> joints 0-15, 1 -> joints 16-31
    const int e0   = blockIdx.x * EPB;

    // ---- stage: base (stride 9), cfg (stride 33), LIM, packed records/targets ----
    {
        const float* gb = base + (size_t)e0 * 7;
        #pragma unroll
        for (int i = t; i < EPB * 7; i += TPB) {
            int r = i / 7, c = i - r * 7;
            s[S_BASE + r * 9 + c] = gb[i];
        }
        const float* gc = cfg + (size_t)e0 * NJ;
        #pragma unroll
        for (int i = t; i < EPB * NJ; i += TPB) {
            s[S_CFG + (i >> 5) * 33 + (i & 31)] = __ldg(gc + i);
        }
        if (t < 32) {   // limit/rest records
            s[S_LIM + t * 4 + 0] = __ldg(jup + t);
            s[S_LIM + t * 4 + 1] = __ldg(jlo + t);
            s[S_LIM + t * 4 + 2] = __ldg(rest + t);
            s[S_LIM + t * 4 + 3] = 0.0f;
        }
        if (t < 16) {   // packed leaf-pair records: pair (jA, jB) = (sp*16+i, sp*16+8+i)
            int sp = t >> 3, i = t & 7;
            int jA = sp * 16 + i, jB = jA + 8;
            float2* d = (float2*)(s + S_PREC) + t * 12;
            float vA[10], vB[10];
            #pragma unroll
            for (int u = 0; u < 2; u++) {
                int j = u ? jB : jA;
                float otx = __ldg(joff + j * 7 + 0), oty = __ldg(joff + j * 7 + 1);
                float otz = __ldg(joff + j * 7 + 2);
                float ox = __ldg(joff + j * 7 + 3), oy = __ldg(joff + j * 7 + 4);
                float oz = __ldg(joff + j * 7 + 5), ow = __ldg(joff + j * 7 + 6);
                float ax = __ldg(jaxis + j * 3 + 0), ay = __ldg(jaxis + j * 3 + 1);
                float az = __ldg(jaxis + j * 3 + 2);
                float* v = u ? vB : vA;
                v[0] = otx; v[1] = oty; v[2] = otz;
                v[3] = ox; v[4] = oy; v[5] = oz; v[6] = ow;
                v[7] = ow * ax + oy * az - oz * ay;
                v[8] = ow * ay + oz * ax - ox * az;
                v[9] = ow * az + ox * ay - oy * ax;
            }
            float PwA = -(vA[3] * __ldg(jaxis + jA * 3 + 0) + vA[4] * __ldg(jaxis + jA * 3 + 1) + vA[5] * __ldg(jaxis + jA * 3 + 2));
            float PwB = -(vB[3] * __ldg(jaxis + jB * 3 + 0) + vB[4] * __ldg(jaxis + jB * 3 + 1) + vB[5] * __ldg(jaxis + jB * 3 + 2));
            #pragma unroll
            for (int k = 0; k < 10; k++) d[k] = make_float2(vA[k], vB[k]);
            d[10] = make_float2(PwA, PwB);
            d[11] = make_float2(0.0f, 0.0f);
        }
        if (t >= 48 && t < 50) {   // packed target pairs (tgt 2p, 2p+1)
            int p = t - 48;
            const float* A = tgt + (2 * p) * 7;
            const float* Bp = tgt + (2 * p + 1) * 7;
            float2* d = (float2*)(s + S_TGT2) + p * 10;
            d[0] = make_float2(-__ldg(A + 0), -__ldg(Bp + 0));
            d[1] = make_float2(-__ldg(A + 1), -__ldg(Bp + 1));
            d[2] = make_float2(-__ldg(A + 2), -__ldg(Bp + 2));
            d[3] = make_float2(-__ldg(A + 3), -__ldg(Bp + 3));
            d[4] = make_float2(-__ldg(A + 4), -__ldg(Bp + 4));
            d[5] = make_float2(-__ldg(A + 5), -__ldg(Bp + 5));
            d[6] = make_float2( __ldg(A + 6),  __ldg(Bp + 6));
            d[7] = make_float2( __ldg(A + 3),  __ldg(Bp + 3));
            d[8] = make_float2( __ldg(A + 4),  __ldg(Bp + 4));
            d[9] = make_float2( __ldg(A + 5),  __ldg(Bp + 5));
        }
        if (t == 50) {   // scalar default base, padded 8
            s[S_DB + 0] = __ldg(dbase + 0); s[S_DB + 1] = __ldg(dbase + 1);
            s[S_DB + 2] = __ldg(dbase + 2); s[S_DB + 3] = 0.0f;
            s[S_DB + 4] = __ldg(dbase + 3); s[S_DB + 5] = __ldg(dbase + 4);
            s[S_DB + 6] = __ldg(dbase + 5); s[S_DB + 7] = __ldg(dbase + 6);
        }
    }
    __syncthreads();

    float* row = s + S_OUT + elem * OUTC;
    const float* cs = s + S_CFG + elem * 33 + seg * 16;   // my 16 angles (JIT loads)
    const ulonglong2* PR = (const ulonglong2*)(s + S_PREC);

    // ---- limit / rest residuals for this thread's 16 joints ----
    #pragma unroll
    for (int i = 0; i < 16; i += 2) {
        const int j = seg * 16 + i;
        float th0 = cs[i], th1 = cs[i + 1];
        float4 A  = *(const float4*)(s + S_LIM + j * 4);
        float4 Bv = *(const float4*)(s + S_LIM + (j + 1) * 4);
        float limA = fmaxf(th0 - A.x, 0.0f)  + fminf(th0 - A.y, 0.0f);
        float limB = fmaxf(th1 - Bv.x, 0.0f) + fminf(th1 - Bv.y, 0.0f);
        *(float2*)(row + 24 + j) = make_float2(limA * 10.0f, limB * 10.0f);
        *(float2*)(row + 56 + j) = make_float2((th0 - A.z) * 0.1f,
                                               (th1 - Bv.z) * 0.1f);
    }

    // ---- ONE packed tree stream: lo = joints [seg*16, +8), hi = [seg*16+8, +8) ----
    V2 St, ta, tb, tc; Q2 Sq, qa, qb, qc;
    {
        const int b8 = seg * 8;
        leaf2(PR, b8 + 0, cs[0], cs[8],  St, Sq);
        leaf2(PR, b8 + 1, cs[1], cs[9],  ta, qa);
        se3_acc2(St, Sq, ta, qa);
        leaf2(PR, b8 + 2, cs[2], cs[10], ta, qa);
        leaf2(PR, b8 + 3, cs[3], cs[11], tb, qb);
        se3_acc2(ta, qa, tb, qb);
        se3_acc2(St, Sq, ta, qa);
        leaf2(PR, b8 + 4, cs[4], cs[12], tc, qc);
        leaf2(PR, b8 + 5, cs[5], cs[13], ta, qa);
        se3_acc2(tc, qc, ta, qa);
        leaf2(PR, b8 + 6, cs[6], cs[14], ta, qa);
        leaf2(PR, b8 + 7, cs[7], cs[15], tb, qb);
        se3_acc2(ta, qa, tb, qb);
        se3_acc2(tc, qc, ta, qa);
        se3_acc2(St, Sq, tc, qc);
    }

    // unpack: lo -> S1 (first 8 joints of my half), hi -> S2 (second 8)
    V S1, S2; Q s1q, s2q;
    f2unp(St.x, S1.x, S2.x); f2unp(St.y, S1.y, S2.y); f2unp(St.z, S1.z, S2.z);
    f2unp(Sq.x, s1q.x, s2q.x); f2unp(Sq.y, s1q.y, s2q.y);
    f2unp(Sq.z, s1q.z, s2q.z); f2unp(Sq.w, s1q.w, s2q.w);

    // E = S1 o S2 (16-joint product of my half)
    V Et; Q Eq;
    se3_comp(S1, s1q, S2, s2q, Et, Eq);

    // ---- base pose (loaded late: stride-9 scalar, conflict-free, pair-broadcast) ----
    V bt; Q bq;
    {
        const float* bs = s + S_BASE + elem * 9;
        bt.x = bs[0]; bt.y = bs[1]; bt.z = bs[2];
        bq.x = bs[3]; bq.y = bs[4]; bq.z = bs[5]; bq.w = bs[6];
    }

    // G = base o E (seg0: T16; seg1: discarded)
    V Gt; Q Gq;
    se3_comp(bt, bq, Et, Eq, Gt, Gq);

    // broadcast lane0's G (=T16) within the pair
    V Lt; Q Lq;
    Lt.x = __shfl_sync(0xffffffffu, Gt.x, 0, 2);
    Lt.y = __shfl_sync(0xffffffffu, Gt.y, 0, 2);
    Lt.z = __shfl_sync(0xffffffffu, Gt.z, 0, 2);
    Lq.x = __shfl_sync(0xffffffffu, Gq.x, 0, 2);
    Lq.y = __shfl_sync(0xffffffffu, Gq.y, 0, 2);
    Lq.z = __shfl_sync(0xffffffffu, Gq.z, 0, 2);
    Lq.w = __shfl_sync(0xffffffffu, Gq.w, 0, 2);

    // prefix select: seg0 -> base, seg1 -> T16
    V Pt; Q Pq;
    Pt.x = seg ? Lt.x : bt.x;  Pt.y = seg ? Lt.y : bt.y;  Pt.z = seg ? Lt.z : bt.z;
    Pq.x = seg ? Lq.x : bq.x;  Pq.y = seg ? Lq.y : bq.y;
    Pq.z = seg ? Lq.z : bq.z;  Pq.w = seg ? Lq.w : bq.w;

    // U1 = P o S1 (T8 / T24), U2 = P o E (T16 / T32)
    V U1t, U2t; Q U1q, U2q;
    se3_comp(Pt, Pq, S1, s1q, U1t, U1q);
    se3_comp(Pt, Pq, Et,  Eq,  U2t, U2q);

    // ---- PACKED pose residuals: (U1,U2) vs target pair seg ----
    {
        V2 at; Q2 aq;
        at.x = f2pack(U1t.x, U2t.x); at.y = f2pack(U1t.y, U2t.y); at.z = f2pack(U1t.z, U2t.z);
        aq.x = f2pack(U1q.x, U2q.x); aq.y = f2pack(U1q.y, U2q.y);
        aq.z = f2pack(U1q.z, U2q.z); aq.w = f2pack(U1q.w, U2q.w);
        V2 rho, phi;
        pose_err2((const u64*)(s + S_TGT2) + seg * 10, at, aq, rho, phi);
        const int kA = seg * 2, kB = seg * 2 + 1;
        float a0, b0, a1, b1, a2, b2, a3, b3, a4, b4, a5, b5;
        f2unp(rho.x, a0, b0); f2unp(rho.y, a1, b1); f2unp(rho.z, a2, b2);
        f2unp(phi.x, a3, b3); f2unp(phi.y, a4, b4); f2unp(phi.z, a5, b5);
        *(float2*)(row + kA * 6 + 0) = make_float2(a0, a1);
        *(float2*)(row + kA * 6 + 2) = make_float2(a2, 0.5f * a3);
        *(float2*)(row + kA * 6 + 4) = make_float2(0.5f * a4, 0.5f * a5);
        *(float2*)(row + kB * 6 + 0) = make_float2(b0, b1);
        *(float2*)(row + kB * 6 + 2) = make_float2(b2, 0.5f * b3);
        *(float2*)(row + kB * 6 + 4) = make_float2(0.5f * b4, 0.5f * b5);
    }

    // ---- base residuals: all 4 warps, lanes 0-15, one element each ----
    {
        const int lane = t & 31;
        const int w    = t >> 5;
        if (lane < 16) {
            const int el = w * 16 + lane;   // 0..63
            const float* bs = s + S_BASE + el * 9;
            V rho, phi;
            pose_err_log(s + S_DB, V{bs[0], bs[1], bs[2]},
                         Q{bs[3], bs[4], bs[5], bs[6]}, rho, phi);
            float* r2 = s + S_OUT + el * OUTC;
            *(float2*)(r2 + 88) = make_float2(rho.x * 5.0f, rho.y * 5.0f);
            *(float2*)(r2 + 90) = make_float2(rho.z * 5.0f, phi.x * 5.0f);
            *(float2*)(r2 + 92) = make_float2(phi.y * 5.0f, phi.z * 5.0f);
        }
    }

    __syncthreads();

    // ---- flat vectorized flush: EPB*OUTC floats = 1504 float4 ----
    {
        float4* go4 = (float4*)(out + (size_t)e0 * OUTC);
        const float4* s4 = (const float4*)(s + S_OUT);
        for (int f = t; f < EPB * OUTC / 4; f += TPB) go4[f] = s4[f];
    }
}

extern "C" void kernel_launch(void* const* d_in, const int* in_sizes, int n_in,
                              void* d_out, int out_size) {
    const float* cfg   = (const float*)d_in[0];
    const float* base  = (const float*)d_in[1];
    const float* tgt   = (const float*)d_in[2];
    const float* dbase = (const float*)d_in[3];
    const float* rest  = (const float*)d_in[4];
    const float* joff  = (const float*)d_in[5];
    const float* jaxis = (const float*)d_in[6];
    const float* jlo   = (const float*)d_in[7];
    const float* jup   = (const float*)d_in[8];
    float* out = (float*)d_out;

    const int smem_bytes = S_TOTAL * sizeof(float);   // 37216
    cudaFuncSetAttribute(ik_residual_kernel,
                         cudaFuncAttributeMaxDynamicSharedMemorySize, smem_bytes);

    int B = in_sizes[0] / NJ;     // 65536
    int nblocks = B / EPB;        // 1024

    ik_residual_kernel<<<nblocks, TPB, smem_bytes>>>(cfg, base, tgt, dbase, rest,
                                                     joff, jaxis, jlo, jup, out);
}